// round 3
// baseline (speedup 1.0000x reference)
#include <cuda_runtime.h>
#include <math.h>

#define NN 100000
#define NE 1600000
#define SCAN_B 512
#define SCAN_G 196   // ceil(100000/512)

// ---------------- scratch (__device__ globals; no allocation) ----------------
__device__ __align__(16) int   g_rowptr[NN + 1];
__device__ __align__(16) int   g_cursor[NN];      // histogram counts, then fill cursors
__device__ __align__(16) int   g_csr[NE];         // src indices bucketed by dst
__device__ __align__(16) float g_pq[NN * 32];     // per node: [p2(16) | q2(16)]
__device__ unsigned long long  g_state[SCAN_G];   // lookback: (value<<2)|flag
__device__ int                 g_ticket;

// ---------------- packed f32x2 helpers ----------------
__device__ __forceinline__ unsigned long long bcast2(float a) {
    unsigned long long r;
    asm("mov.b64 %0,{%1,%1};" : "=l"(r) : "f"(a));
    return r;
}
__device__ __forceinline__ float2 unpk2(unsigned long long v) {
    float2 r;
    asm("mov.b64 {%0,%1},%2;" : "=f"(r.x), "=f"(r.y) : "l"(v));
    return r;
}
#define FMA2(d, a, b, c) asm("fma.rn.f32x2 %0,%1,%2,%3;" : "=l"(d) : "l"(a), "l"(b), "l"(c))
#define ADD2(d, a, b)    asm("add.rn.f32x2 %0,%1,%2;"    : "=l"(d) : "l"(a), "l"(b))
#define MUL2(d, a, b)    asm("mul.rn.f32x2 %0,%1,%2;"    : "=l"(d) : "l"(a), "l"(b))

// ---------------------------------------------------------------------------
// Histogram of dst
// ---------------------------------------------------------------------------
__global__ void k_hist(const int* __restrict__ ei) {
    int e = blockIdx.x * blockDim.x + threadIdx.x;
    if (e < NE) atomicAdd(&g_cursor[__ldg(ei + NE + e)], 1);
}

__device__ __forceinline__ int warp_incl_scan(int v) {
    int lane = threadIdx.x & 31;
#pragma unroll
    for (int d = 1; d < 32; d <<= 1) {
        int t = __shfl_up_sync(0xFFFFFFFFu, v, d);
        if (lane >= d) v += t;
    }
    return v;
}

// ---------------------------------------------------------------------------
// Single-pass exclusive scan (decoupled lookback, ticket-ordered blocks)
// ---------------------------------------------------------------------------
__global__ void __launch_bounds__(512) k_scan() {
    __shared__ int ws[16];
    __shared__ int sbid;
    __shared__ int s_prefix;
    int tid = threadIdx.x;
    if (tid == 0) { sbid = atomicAdd(&g_ticket, 1); s_prefix = 0; }
    __syncthreads();
    int bid = sbid;
    int g = bid * 512 + tid;
    int v = (g < NN) ? g_cursor[g] : 0;
    int inc = warp_incl_scan(v);
    int wid = tid >> 5, lane = tid & 31;
    if (lane == 31) ws[wid] = inc;
    __syncthreads();
    if (wid == 0) {
        int t = (lane < 16) ? ws[lane] : 0;
        t = warp_incl_scan(t);
        if (lane < 16) ws[lane] = t;
    }
    __syncthreads();
    int off = (wid > 0) ? ws[wid - 1] : 0;
    int linc = inc + off;                  // local inclusive

    // publish aggregate (block 0 publishes terminal prefix immediately)
    if (tid == 511) {
        unsigned long long pk = ((unsigned long long)linc << 2) | (bid == 0 ? 2ull : 1ull);
        __threadfence();
        atomicExch(&g_state[bid], pk);
    }
    // lookback
    if (bid > 0 && tid == 0) {
        long long run = 0;
        int p = bid - 1;
        while (true) {
            unsigned long long st;
            do { st = *((volatile unsigned long long*)&g_state[p]); } while ((st & 3ull) == 0);
            run += (long long)(st >> 2);
            if ((st & 3ull) == 2ull) break;
            p--;
        }
        s_prefix = (int)run;
    }
    __syncthreads();
    int pref = s_prefix;
    if (bid > 0 && tid == 511) {
        unsigned long long pk = ((unsigned long long)(pref + linc) << 2) | 2ull;
        __threadfence();
        atomicExch(&g_state[bid], pk);
    }
    int excl = pref + (linc - v);
    if (g < NN) { g_rowptr[g] = excl; g_cursor[g] = excl; }
    if (g == NN) g_rowptr[NN] = excl;   // == NE
}

__global__ void k_fill(const int* __restrict__ ei) {
    int e = blockIdx.x * blockDim.x + threadIdx.x;
    if (e < NE) {
        int src = __ldg(ei + e);
        int dst = __ldg(ei + NE + e);
        int pos = atomicAdd(&g_cursor[dst], 1);
        g_csr[pos] = src;
    }
}

// ---------------------------------------------------------------------------
// Mega kernel: gather mean(x) -> layer1 (relu) -> layer2 projections p2,q2
// 256 threads, 64 nodes / block. Packed f32x2 math everywhere.
// ---------------------------------------------------------------------------
#define SH_STRIDE 68
#define SMEM_FLOATS (4096 + 4096 + 2048 + 64 * SH_STRIDE + 32 + 64)

__global__ void __launch_bounds__(256) mega_kernel(
    const float* __restrict__ x,
    const float* __restrict__ W1l, const float* __restrict__ W1r,
    const float* __restrict__ b1,
    const float* __restrict__ W2l, const float* __restrict__ W2r,
    const float* __restrict__ b2)
{
    extern __shared__ float smem[];
    float* sWl = smem;
    float* sWr = sWl + 4096;
    float* sW2 = sWr + 4096;
    float* sH  = sW2 + 2048;            // 64 x 68 (mean, later h1)
    float* sB  = sH + 64 * SH_STRIDE;   // 32: [0]*16 | b2
    float* sB1 = sB + 32;               // 64

    int tid = threadIdx.x;

    for (int i = tid; i < 1024; i += 256) {
        ((float4*)sWl)[i] = ((const float4*)W1l)[i];
        ((float4*)sWr)[i] = ((const float4*)W1r)[i];
    }
    for (int i = tid; i < 64 * 16; i += 256) {
        int k = i >> 4, j = i & 15;
        sW2[k * 32 + j]      = W2l[i];
        sW2[k * 32 + 16 + j] = W2r[i];
    }
    if (tid < 16) { sB[tid] = 0.f; sB[16 + tid] = b2[tid]; }
    if (tid < 64) sB1[tid] = b1[tid];

    // ---- gather: mean of x over in-neighbors, 4 threads/node, packed adds ----
    {
        int nl = tid >> 2;
        int c  = tid & 3;
        int node = blockIdx.x * 64 + nl;
        int s = 0, e = 0;
        if (node < NN) { s = __ldg(g_rowptr + node); e = __ldg(g_rowptr + node + 1); }
        unsigned long long acc[8];
#pragma unroll
        for (int j = 0; j < 8; j++) acc[j] = 0ull;
        const ulonglong2* x2 = (const ulonglong2*)x;
        for (int i = s; i < e; i++) {
            int src = __ldg(g_csr + i);
            const ulonglong2* row = x2 + (size_t)src * 16 + c;
#pragma unroll
            for (int j = 0; j < 4; j++) {
                ulonglong2 v = __ldg(row + j * 4);
                ADD2(acc[2 * j],     acc[2 * j],     v.x);
                ADD2(acc[2 * j + 1], acc[2 * j + 1], v.y);
            }
        }
        unsigned long long I = bcast2(1.f / fmaxf((float)(e - s), 1.f));
        ulonglong2* dstp = (ulonglong2*)(sH + nl * SH_STRIDE);
#pragma unroll
        for (int j = 0; j < 4; j++) {
            ulonglong2 o;
            MUL2(o.x, acc[2 * j],     I);
            MUL2(o.y, acc[2 * j + 1], I);
            dstp[j * 4 + c] = o;
        }
    }
    __syncthreads();

    // ---- phase A: h1 = relu(mean @ W1l + x @ W1r + b1); 2 nodes x 8 cols ----
    int js = tid & 7, ns = tid >> 3;
    int jb = js * 8;
    int l0 = ns * 2, l1 = l0 + 1;
    int n0 = blockIdx.x * 64 + l0, n1 = n0 + 1;
    bool v0 = n0 < NN, v1 = n1 < NN;
    const float4* x4 = (const float4*)x;
    float4 z4 = make_float4(0.f, 0.f, 0.f, 0.f);

    unsigned long long acc0[4], acc1[4];
#pragma unroll
    for (int j = 0; j < 4; j++) { acc0[j] = 0ull; acc1[j] = 0ull; }

#pragma unroll 4
    for (int k4 = 0; k4 < 16; k4++) {
        float4 a0 = *(float4*)(sH + l0 * SH_STRIDE + k4 * 4);
        float4 a1 = *(float4*)(sH + l1 * SH_STRIDE + k4 * 4);
        float4 X0 = v0 ? __ldg(x4 + (size_t)n0 * 16 + k4) : z4;
        float4 X1 = v1 ? __ldg(x4 + (size_t)n1 * 16 + k4) : z4;
        float av0[4] = {a0.x, a0.y, a0.z, a0.w};
        float av1[4] = {a1.x, a1.y, a1.z, a1.w};
        float xv0[4] = {X0.x, X0.y, X0.z, X0.w};
        float xv1[4] = {X1.x, X1.y, X1.z, X1.w};
#pragma unroll
        for (int kk = 0; kk < 4; kk++) {
            int k = k4 * 4 + kk;
            ulonglong2 wl01 = *(const ulonglong2*)(sWl + k * 64 + jb);
            ulonglong2 wl23 = *(const ulonglong2*)(sWl + k * 64 + jb + 4);
            ulonglong2 wr01 = *(const ulonglong2*)(sWr + k * 64 + jb);
            ulonglong2 wr23 = *(const ulonglong2*)(sWr + k * 64 + jb + 4);
            unsigned long long A0 = bcast2(av0[kk]);
            unsigned long long A1 = bcast2(av1[kk]);
            unsigned long long B0 = bcast2(xv0[kk]);
            unsigned long long B1 = bcast2(xv1[kk]);
            FMA2(acc0[0], A0, wl01.x, acc0[0]);
            FMA2(acc0[1], A0, wl01.y, acc0[1]);
            FMA2(acc0[2], A0, wl23.x, acc0[2]);
            FMA2(acc0[3], A0, wl23.y, acc0[3]);
            FMA2(acc1[0], A1, wl01.x, acc1[0]);
            FMA2(acc1[1], A1, wl01.y, acc1[1]);
            FMA2(acc1[2], A1, wl23.x, acc1[2]);
            FMA2(acc1[3], A1, wl23.y, acc1[3]);
            FMA2(acc0[0], B0, wr01.x, acc0[0]);
            FMA2(acc0[1], B0, wr01.y, acc0[1]);
            FMA2(acc0[2], B0, wr23.x, acc0[2]);
            FMA2(acc0[3], B0, wr23.y, acc0[3]);
            FMA2(acc1[0], B1, wr01.x, acc1[0]);
            FMA2(acc1[1], B1, wr01.y, acc1[1]);
            FMA2(acc1[2], B1, wr23.x, acc1[2]);
            FMA2(acc1[3], B1, wr23.y, acc1[3]);
        }
    }

    float o0[8], o1[8];
#pragma unroll
    for (int p = 0; p < 4; p++) {
        float2 u0 = unpk2(acc0[p]);
        float2 u1 = unpk2(acc1[p]);
        o0[2 * p]     = fmaxf(u0.x + sB1[jb + 2 * p],     0.f);
        o0[2 * p + 1] = fmaxf(u0.y + sB1[jb + 2 * p + 1], 0.f);
        o1[2 * p]     = fmaxf(u1.x + sB1[jb + 2 * p],     0.f);
        o1[2 * p + 1] = fmaxf(u1.y + sB1[jb + 2 * p + 1], 0.f);
    }
    __syncthreads();   // done reading mean from sH
    *(float4*)(sH + l0 * SH_STRIDE + jb)     = *(float4*)(o0);
    *(float4*)(sH + l0 * SH_STRIDE + jb + 4) = *(float4*)(o0 + 4);
    *(float4*)(sH + l1 * SH_STRIDE + jb)     = *(float4*)(o1);
    *(float4*)(sH + l1 * SH_STRIDE + jb + 4) = *(float4*)(o1 + 4);
    __syncthreads();

    // ---- phase B: [p2|q2] = h1 @ [W2l|W2r] + [0|b2]; 1 node x 8 cols ----
    {
        int nl = tid >> 2;
        int cs = tid & 3;
        int cb = cs * 8;
        int node = blockIdx.x * 64 + nl;
        unsigned long long accB[4];
#pragma unroll
        for (int j = 0; j < 4; j++) accB[j] = 0ull;
#pragma unroll 4
        for (int k4 = 0; k4 < 16; k4++) {
            float4 h4 = *(float4*)(sH + nl * SH_STRIDE + k4 * 4);
            float hv[4] = {h4.x, h4.y, h4.z, h4.w};
#pragma unroll
            for (int kk = 0; kk < 4; kk++) {
                int k = k4 * 4 + kk;
                ulonglong2 w01 = *(const ulonglong2*)(sW2 + k * 32 + cb);
                ulonglong2 w23 = *(const ulonglong2*)(sW2 + k * 32 + cb + 4);
                unsigned long long H = bcast2(hv[kk]);
                FMA2(accB[0], H, w01.x, accB[0]);
                FMA2(accB[1], H, w01.y, accB[1]);
                FMA2(accB[2], H, w23.x, accB[2]);
                FMA2(accB[3], H, w23.y, accB[3]);
            }
        }
        if (node < NN) {
            float o[8];
#pragma unroll
            for (int p = 0; p < 4; p++) {
                float2 u = unpk2(accB[p]);
                o[2 * p]     = u.x + sB[cb + 2 * p];
                o[2 * p + 1] = u.y + sB[cb + 2 * p + 1];
            }
            *(float4*)(g_pq + (size_t)node * 32 + cb)     = *(float4*)(o);
            *(float4*)(g_pq + (size_t)node * 32 + cb + 4) = *(float4*)(o + 4);
        }
    }
}

// ---------------------------------------------------------------------------
// Final: gather mean(p2) + q2 -> log_softmax -> out. 4 threads/node.
// ---------------------------------------------------------------------------
__global__ void __launch_bounds__(256) final_kernel(float* __restrict__ out) {
    int tid = threadIdx.x;
    int node = blockIdx.x * 64 + (tid >> 2);
    int c = tid & 3;
    bool nv = node < NN;
    int s = 0, e = 0;
    if (nv) { s = __ldg(g_rowptr + node); e = __ldg(g_rowptr + node + 1); }
    float4 acc = make_float4(0.f, 0.f, 0.f, 0.f);
    const float4* pq4 = (const float4*)g_pq;
    for (int i = s; i < e; i++) {
        int src = __ldg(g_csr + i);
        float4 v = __ldg(pq4 + (size_t)src * 8 + c);
        acc.x += v.x; acc.y += v.y; acc.z += v.z; acc.w += v.w;
    }
    float invd = 1.f / fmaxf((float)(e - s), 1.f);
    float4 q = nv ? __ldg(pq4 + (size_t)node * 8 + 4 + c)
                  : make_float4(0.f, 0.f, 0.f, 0.f);
    float v[4];
    v[0] = acc.x * invd + q.x;
    v[1] = acc.y * invd + q.y;
    v[2] = acc.z * invd + q.z;
    v[3] = acc.w * invd + q.w;

    float m = fmaxf(fmaxf(v[0], v[1]), fmaxf(v[2], v[3]));
    m = fmaxf(m, __shfl_xor_sync(0xFFFFFFFFu, m, 1));
    m = fmaxf(m, __shfl_xor_sync(0xFFFFFFFFu, m, 2));
    float sum = expf(v[0] - m) + expf(v[1] - m) + expf(v[2] - m) + expf(v[3] - m);
    sum += __shfl_xor_sync(0xFFFFFFFFu, sum, 1);
    sum += __shfl_xor_sync(0xFFFFFFFFu, sum, 2);
    float lse = m + logf(sum);

    if (nv) {
        float4 o;
        o.x = v[0] - lse; o.y = v[1] - lse; o.z = v[2] - lse; o.w = v[3] - lse;
        ((float4*)out)[(size_t)node * 4 + c] = o;
    }
}

// ---------------------------------------------------------------------------
extern "C" void kernel_launch(void* const* d_in, const int* in_sizes, int n_in,
                              void* d_out, int out_size) {
    const float* x   = (const float*)d_in[0];
    const int*   ei  = (const int*)d_in[1];
    const float* W1l = (const float*)d_in[2];
    const float* W1r = (const float*)d_in[3];
    const float* b1  = (const float*)d_in[4];
    const float* W2l = (const float*)d_in[5];
    const float* W2r = (const float*)d_in[6];
    const float* b2  = (const float*)d_in[7];
    float* out = (float*)d_out;

    void *p_cursor, *p_state, *p_ticket;
    cudaGetSymbolAddress(&p_cursor, g_cursor);
    cudaGetSymbolAddress(&p_state,  g_state);
    cudaGetSymbolAddress(&p_ticket, g_ticket);
    cudaMemsetAsync(p_cursor, 0, NN * sizeof(int));
    cudaMemsetAsync(p_state,  0, SCAN_G * sizeof(unsigned long long));
    cudaMemsetAsync(p_ticket, 0, sizeof(int));

    k_hist<<<(NE + 255) / 256, 256>>>(ei);
    k_scan<<<SCAN_G, 512>>>();
    k_fill<<<(NE + 255) / 256, 256>>>(ei);

    cudaFuncSetAttribute(mega_kernel,
                         cudaFuncAttributeMaxDynamicSharedMemorySize,
                         SMEM_FLOATS * sizeof(float));
    mega_kernel<<<(NN + 63) / 64, 256, SMEM_FLOATS * sizeof(float)>>>(
        x, W1l, W1r, b1, W2l, W2r, b2);

    final_kernel<<<(NN + 63) / 64, 256>>>(out);
}

// round 5
// speedup vs baseline: 1.1617x; 1.1617x over previous
#include <cuda_runtime.h>
#include <math.h>

#define NN 100000
#define NE 1600000
#define SCAN_G 196   // ceil(100000/512)

// ---------------- scratch (__device__ globals; no allocation) ----------------
__device__ __align__(16) int   g_rowptr[NN + 1];
__device__ __align__(16) int   g_cursor[NN];
__device__ __align__(16) int   g_csr[NE];
__device__ __align__(16) float g_mean[NN * 64];   // mean of x over in-neighbors
__device__ __align__(16) float g_pq[NN * 32];     // per node: [p2(16) | q2(16)]
__device__ unsigned long long  g_state[SCAN_G];
__device__ int                 g_ticket;

// ---------------- packed f32x2 helpers ----------------
__device__ __forceinline__ unsigned long long bcast2(float a) {
    unsigned long long r;
    asm("mov.b64 %0,{%1,%1};" : "=l"(r) : "f"(a));
    return r;
}
__device__ __forceinline__ float2 unpk2(unsigned long long v) {
    float2 r;
    asm("mov.b64 {%0,%1},%2;" : "=f"(r.x), "=f"(r.y) : "l"(v));
    return r;
}
#define FMA2(d, a, b, c) asm("fma.rn.f32x2 %0,%1,%2,%3;" : "=l"(d) : "l"(a), "l"(b), "l"(c))
#define ADD2(d, a, b)    asm("add.rn.f32x2 %0,%1,%2;"    : "=l"(d) : "l"(a), "l"(b))
#define MUL2(d, a, b)    asm("mul.rn.f32x2 %0,%1,%2;"    : "=l"(d) : "l"(a), "l"(b))

// ---------------------------------------------------------------------------
// CSR build
// ---------------------------------------------------------------------------
__global__ void k_hist(const int* __restrict__ ei) {
    int e = blockIdx.x * blockDim.x + threadIdx.x;
    if (e < NE) atomicAdd(&g_cursor[__ldg(ei + NE + e)], 1);
}

__device__ __forceinline__ int warp_incl_scan(int v) {
    int lane = threadIdx.x & 31;
#pragma unroll
    for (int d = 1; d < 32; d <<= 1) {
        int t = __shfl_up_sync(0xFFFFFFFFu, v, d);
        if (lane >= d) v += t;
    }
    return v;
}

__global__ void __launch_bounds__(512) k_scan() {
    __shared__ int ws[16];
    __shared__ int sbid;
    __shared__ int s_prefix;
    int tid = threadIdx.x;
    if (tid == 0) { sbid = atomicAdd(&g_ticket, 1); s_prefix = 0; }
    __syncthreads();
    int bid = sbid;
    int g = bid * 512 + tid;
    int v = (g < NN) ? g_cursor[g] : 0;
    int inc = warp_incl_scan(v);
    int wid = tid >> 5, lane = tid & 31;
    if (lane == 31) ws[wid] = inc;
    __syncthreads();
    if (wid == 0) {
        int t = (lane < 16) ? ws[lane] : 0;
        t = warp_incl_scan(t);
        if (lane < 16) ws[lane] = t;
    }
    __syncthreads();
    int off = (wid > 0) ? ws[wid - 1] : 0;
    int linc = inc + off;

    if (tid == 511) {
        unsigned long long pk = ((unsigned long long)linc << 2) | (bid == 0 ? 2ull : 1ull);
        __threadfence();
        atomicExch(&g_state[bid], pk);
    }
    if (bid > 0 && tid == 0) {
        long long run = 0;
        int p = bid - 1;
        while (true) {
            unsigned long long st;
            do { st = *((volatile unsigned long long*)&g_state[p]); } while ((st & 3ull) == 0);
            run += (long long)(st >> 2);
            if ((st & 3ull) == 2ull) break;
            p--;
        }
        s_prefix = (int)run;
    }
    __syncthreads();
    int pref = s_prefix;
    if (bid > 0 && tid == 511) {
        unsigned long long pk = ((unsigned long long)(pref + linc) << 2) | 2ull;
        __threadfence();
        atomicExch(&g_state[bid], pk);
    }
    int excl = pref + (linc - v);
    if (g < NN) { g_rowptr[g] = excl; g_cursor[g] = excl; }
    if (g == NN) g_rowptr[NN] = excl;
}

__global__ void k_fill(const int* __restrict__ ei) {
    int e = blockIdx.x * blockDim.x + threadIdx.x;
    if (e < NE) {
        int src = __ldg(ei + e);
        int dst = __ldg(ei + NE + e);
        int pos = atomicAdd(&g_cursor[dst], 1);
        g_csr[pos] = src;
    }
}

// ---------------------------------------------------------------------------
// Gather 1: g_mean[n] = mean of x[src] over in-neighbors.
// 16 lanes per node, 1 LDG.128 per lane per neighbor. Unrolled x4.
// ---------------------------------------------------------------------------
__global__ void __launch_bounds__(256) gather1_kernel(const float* __restrict__ x) {
    int node = blockIdx.x * 16 + (threadIdx.x >> 4);
    int c = threadIdx.x & 15;
    if (node >= NN) return;
    int s = __ldg(g_rowptr + node);
    int e = __ldg(g_rowptr + node + 1);
    unsigned long long a0 = 0ull, a1 = 0ull;
    const ulonglong2* x2 = (const ulonglong2*)x;
    int i = s;
    for (; i + 4 <= e; i += 4) {
        int s0 = __ldg(g_csr + i);
        int s1 = __ldg(g_csr + i + 1);
        int s2 = __ldg(g_csr + i + 2);
        int s3 = __ldg(g_csr + i + 3);
        ulonglong2 v0 = __ldg(x2 + (size_t)s0 * 16 + c);
        ulonglong2 v1 = __ldg(x2 + (size_t)s1 * 16 + c);
        ulonglong2 v2 = __ldg(x2 + (size_t)s2 * 16 + c);
        ulonglong2 v3 = __ldg(x2 + (size_t)s3 * 16 + c);
        ADD2(a0, a0, v0.x); ADD2(a1, a1, v0.y);
        ADD2(a0, a0, v1.x); ADD2(a1, a1, v1.y);
        ADD2(a0, a0, v2.x); ADD2(a1, a1, v2.y);
        ADD2(a0, a0, v3.x); ADD2(a1, a1, v3.y);
    }
    for (; i < e; i++) {
        int s0 = __ldg(g_csr + i);
        ulonglong2 v0 = __ldg(x2 + (size_t)s0 * 16 + c);
        ADD2(a0, a0, v0.x); ADD2(a1, a1, v0.y);
    }
    unsigned long long I = bcast2(1.f / fmaxf((float)(e - s), 1.f));
    ulonglong2 o;
    MUL2(o.x, a0, I);
    MUL2(o.y, a1, I);
    ((ulonglong2*)g_mean)[(size_t)node * 16 + c] = o;
}

// ---------------------------------------------------------------------------
// Dense: thread-per-node. h1 = relu(mean@W1l + x@W1r + b1) in registers,
// then [p2|q2] = h1@[W2l|W2r] + [0|b2] -> g_pq.
// Weights read warp-uniform from smem (broadcast, crossbar-free).
// Features staged per 16-k block into [k][node] tiles (stride 257).
// ---------------------------------------------------------------------------
#define TS 257
#define DSM_FLOATS (4096 + 4096 + 2048 + 2 * 16 * TS + 32 + 64)

__global__ void __launch_bounds__(256) dense_kernel(
    const float* __restrict__ x,
    const float* __restrict__ W1l, const float* __restrict__ W1r,
    const float* __restrict__ b1,
    const float* __restrict__ W2l, const float* __restrict__ W2r,
    const float* __restrict__ b2)
{
    extern __shared__ float smem[];
    float* sWl = smem;                 // [k*64 + j]
    float* sWr = sWl + 4096;
    float* sW2 = sWr + 4096;           // [k*32 + j]
    float* sA  = sW2 + 2048;           // [k*TS + node_local], 16 k
    float* sX  = sA + 16 * TS;
    float* sB2 = sX + 16 * TS;         // 32
    float* sB1 = sB2 + 32;             // 64

    int tid = threadIdx.x;
    int nbase = blockIdx.x * 256;
    int node = nbase + tid;
    bool valid = node < NN;

    for (int i = tid; i < 1024; i += 256) {
        ((float4*)sWl)[i] = ((const float4*)W1l)[i];
        ((float4*)sWr)[i] = ((const float4*)W1r)[i];
    }
    for (int i = tid; i < 64 * 16; i += 256) {
        int k = i >> 4, j = i & 15;
        sW2[k * 32 + j]      = W2l[i];
        sW2[k * 32 + 16 + j] = W2r[i];
    }
    if (tid < 16) { sB2[tid] = 0.f; sB2[16 + tid] = b2[tid]; }
    if (tid < 64) sB1[tid] = b1[tid];

    unsigned long long accA[32];
#pragma unroll
    for (int j = 0; j < 32; j++) accA[j] = 0ull;

    const float4* x4 = (const float4*)x;
    const float4* m4 = (const float4*)g_mean;
    float4 z4 = make_float4(0.f, 0.f, 0.f, 0.f);

    for (int kb = 0; kb < 4; kb++) {
        __syncthreads();
        for (int i = tid; i < 1024; i += 256) {
            int nl = i >> 2, cc = i & 3;
            int gn = nbase + nl;
            float4 va = (gn < NN) ? __ldg(m4 + (size_t)gn * 16 + kb * 4 + cc) : z4;
            float4 vx = (gn < NN) ? __ldg(x4 + (size_t)gn * 16 + kb * 4 + cc) : z4;
            int kr = cc * 4;
            sA[(kr + 0) * TS + nl] = va.x;
            sA[(kr + 1) * TS + nl] = va.y;
            sA[(kr + 2) * TS + nl] = va.z;
            sA[(kr + 3) * TS + nl] = va.w;
            sX[(kr + 0) * TS + nl] = vx.x;
            sX[(kr + 1) * TS + nl] = vx.y;
            sX[(kr + 2) * TS + nl] = vx.z;
            sX[(kr + 3) * TS + nl] = vx.w;
        }
        __syncthreads();
#pragma unroll
        for (int k = 0; k < 16; k++) {
            int kg = kb * 16 + k;
            unsigned long long A = bcast2(sA[k * TS + tid]);
            unsigned long long X = bcast2(sX[k * TS + tid]);
            const ulonglong2* wl = (const ulonglong2*)(sWl + kg * 64);
            const ulonglong2* wr = (const ulonglong2*)(sWr + kg * 64);
#pragma unroll
            for (int jh = 0; jh < 16; jh++) {
                ulonglong2 w = wl[jh];
                FMA2(accA[2 * jh],     A, w.x, accA[2 * jh]);
                FMA2(accA[2 * jh + 1], A, w.y, accA[2 * jh + 1]);
            }
#pragma unroll
            for (int jh = 0; jh < 16; jh++) {
                ulonglong2 w = wr[jh];
                FMA2(accA[2 * jh],     X, w.x, accA[2 * jh]);
                FMA2(accA[2 * jh + 1], X, w.y, accA[2 * jh + 1]);
            }
        }
    }

    float h1[64];
#pragma unroll
    for (int p = 0; p < 32; p++) {
        float2 u = unpk2(accA[p]);
        h1[2 * p]     = fmaxf(u.x + sB1[2 * p],     0.f);
        h1[2 * p + 1] = fmaxf(u.y + sB1[2 * p + 1], 0.f);
    }

    unsigned long long accB[16];
#pragma unroll
    for (int j = 0; j < 16; j++) accB[j] = 0ull;
#pragma unroll 8
    for (int k = 0; k < 64; k++) {
        unsigned long long H = bcast2(h1[k]);
        const ulonglong2* w2 = (const ulonglong2*)(sW2 + k * 32);
#pragma unroll
        for (int jh = 0; jh < 8; jh++) {
            ulonglong2 w = w2[jh];
            FMA2(accB[2 * jh],     H, w.x, accB[2 * jh]);
            FMA2(accB[2 * jh + 1], H, w.y, accB[2 * jh + 1]);
        }
    }
    if (valid) {
        float o[32];
#pragma unroll
        for (int p = 0; p < 16; p++) {
            float2 u = unpk2(accB[p]);
            o[2 * p]     = u.x + sB2[2 * p];
            o[2 * p + 1] = u.y + sB2[2 * p + 1];
        }
        float4* dst = (float4*)(g_pq + (size_t)node * 32);
#pragma unroll
        for (int q = 0; q < 8; q++) dst[q] = *(float4*)(o + 4 * q);
    }
}

// ---------------------------------------------------------------------------
// Final: gather mean(p2) + q2 -> log_softmax -> out. 4 lanes/node, unroll x4.
// g_pq row = 32 floats = 8 ulonglong2 -> neighbor stride is src*8 (BUGFIX).
// ---------------------------------------------------------------------------
__global__ void __launch_bounds__(256) final_kernel(float* __restrict__ out) {
    int tid = threadIdx.x;
    int node = blockIdx.x * 64 + (tid >> 2);
    int c = tid & 3;
    bool nv = node < NN;
    int s = 0, e = 0;
    if (nv) { s = __ldg(g_rowptr + node); e = __ldg(g_rowptr + node + 1); }
    unsigned long long a0 = 0ull, a1 = 0ull;
    const ulonglong2* pq2 = (const ulonglong2*)g_pq;
    int i = s;
    for (; i + 4 <= e; i += 4) {
        int s0 = __ldg(g_csr + i);
        int s1 = __ldg(g_csr + i + 1);
        int s2 = __ldg(g_csr + i + 2);
        int s3 = __ldg(g_csr + i + 3);
        ulonglong2 v0 = __ldg(pq2 + (size_t)s0 * 8 + c);
        ulonglong2 v1 = __ldg(pq2 + (size_t)s1 * 8 + c);
        ulonglong2 v2 = __ldg(pq2 + (size_t)s2 * 8 + c);
        ulonglong2 v3 = __ldg(pq2 + (size_t)s3 * 8 + c);
        ADD2(a0, a0, v0.x); ADD2(a1, a1, v0.y);
        ADD2(a0, a0, v1.x); ADD2(a1, a1, v1.y);
        ADD2(a0, a0, v2.x); ADD2(a1, a1, v2.y);
        ADD2(a0, a0, v3.x); ADD2(a1, a1, v3.y);
    }
    for (; i < e; i++) {
        int s0 = __ldg(g_csr + i);
        ulonglong2 v0 = __ldg(pq2 + (size_t)s0 * 8 + c);
        ADD2(a0, a0, v0.x); ADD2(a1, a1, v0.y);
    }
    float invd = 1.f / fmaxf((float)(e - s), 1.f);
    float2 u0 = unpk2(a0), u1 = unpk2(a1);
    float4 q = nv ? __ldg((const float4*)g_pq + (size_t)node * 8 + 4 + c)
                  : make_float4(0.f, 0.f, 0.f, 0.f);
    float v[4];
    v[0] = u0.x * invd + q.x;
    v[1] = u0.y * invd + q.y;
    v[2] = u1.x * invd + q.z;
    v[3] = u1.y * invd + q.w;

    float m = fmaxf(fmaxf(v[0], v[1]), fmaxf(v[2], v[3]));
    m = fmaxf(m, __shfl_xor_sync(0xFFFFFFFFu, m, 1));
    m = fmaxf(m, __shfl_xor_sync(0xFFFFFFFFu, m, 2));
    float sum = expf(v[0] - m) + expf(v[1] - m) + expf(v[2] - m) + expf(v[3] - m);
    sum += __shfl_xor_sync(0xFFFFFFFFu, sum, 1);
    sum += __shfl_xor_sync(0xFFFFFFFFu, sum, 2);
    float lse = m + logf(sum);

    if (nv) {
        float4 o;
        o.x = v[0] - lse; o.y = v[1] - lse; o.z = v[2] - lse; o.w = v[3] - lse;
        ((float4*)out)[(size_t)node * 4 + c] = o;
    }
}

// ---------------------------------------------------------------------------
extern "C" void kernel_launch(void* const* d_in, const int* in_sizes, int n_in,
                              void* d_out, int out_size) {
    const float* x   = (const float*)d_in[0];
    const int*   ei  = (const int*)d_in[1];
    const float* W1l = (const float*)d_in[2];
    const float* W1r = (const float*)d_in[3];
    const float* b1  = (const float*)d_in[4];
    const float* W2l = (const float*)d_in[5];
    const float* W2r = (const float*)d_in[6];
    const float* b2  = (const float*)d_in[7];
    float* out = (float*)d_out;

    void *p_cursor, *p_state, *p_ticket;
    cudaGetSymbolAddress(&p_cursor, g_cursor);
    cudaGetSymbolAddress(&p_state,  g_state);
    cudaGetSymbolAddress(&p_ticket, g_ticket);
    cudaMemsetAsync(p_cursor, 0, NN * sizeof(int));
    cudaMemsetAsync(p_state,  0, SCAN_G * sizeof(unsigned long long));
    cudaMemsetAsync(p_ticket, 0, sizeof(int));

    k_hist<<<(NE + 255) / 256, 256>>>(ei);
    k_scan<<<SCAN_G, 512>>>();
    k_fill<<<(NE + 255) / 256, 256>>>(ei);

    gather1_kernel<<<(NN + 15) / 16, 256>>>(x);

    cudaFuncSetAttribute(dense_kernel,
                         cudaFuncAttributeMaxDynamicSharedMemorySize,
                         DSM_FLOATS * sizeof(float));
    dense_kernel<<<(NN + 255) / 256, 256, DSM_FLOATS * sizeof(float)>>>(
        x, W1l, W1r, b1, W2l, W2r, b2);

    final_kernel<<<(NN + 63) / 64, 256>>>(out);
}